// round 2
// baseline (speedup 1.0000x reference)
#include <cuda_runtime.h>

#define LRELU_SLOPE 0.01f
#define BN_EPS 1e-5f

// Ping-pong scratch: max intermediate is 2*64*512*512 = 33,554,432 floats (134 MB).
__device__ float g_bufA[33554432];
__device__ float g_bufB[33554432];

// ---------------------------------------------------------------------------
// Encoder / bottleneck 3x3 conv kernel.
//   MODE 0: plain SAME conv (Hin==Hout)
//   MODE 1: fused stride-2 subsample of conv output: out(oy,ox)=conv(in)(2oy,2ox); Hin=2*Hout
// Each thread computes PX consecutive output x positions for 8 output channels.
// Weights for an 8ci x 8co chunk are staged in shared memory (broadcast LDS).
// ---------------------------------------------------------------------------
template<int MODE, int PX, bool RELU>
__global__ void conv3x3_kernel(const float* __restrict__ in,
                               const float* __restrict__ wgt,
                               const float* __restrict__ bias,
                               float* __restrict__ out,
                               int N, int Cin, int Hin, int Win,
                               int Cout, int Hout, int Wout)
{
    __shared__ float sw[8 * 9 * 8];   // sw[ci][k][co]

    const int coChunks = Cout >> 3;
    const int z  = blockIdx.z;
    const int n  = z / coChunks;
    const int cob = (z - n * coChunks) << 3;

    const int oy  = blockIdx.y * blockDim.y + threadIdx.y;
    const int ox0 = (blockIdx.x * blockDim.x + threadIdx.x) * PX;
    const bool active = (oy < Hout) && (ox0 < Wout);

    float acc[PX][8];
#pragma unroll
    for (int p = 0; p < PX; p++)
#pragma unroll
        for (int c = 0; c < 8; c++) acc[p][c] = 0.f;

    const int tid = threadIdx.y * blockDim.x + threadIdx.x;
    const int nthreads = blockDim.x * blockDim.y;

    for (int ci0 = 0; ci0 < Cin; ci0 += 8) {
        const int cc = min(8, Cin - ci0);

        __syncthreads();
        // cooperative load of the weight chunk: sw[ci*72 + k*8 + co]
        for (int e = tid; e < 8 * 9 * 8; e += nthreads) {
            int ci = e / 72;
            int r  = e - ci * 72;
            int k  = r >> 3;
            int co = r & 7;
            float v = 0.f;
            if (ci < cc)
                v = wgt[((size_t)(cob + co) * Cin + (ci0 + ci)) * 9 + k];
            sw[e] = v;
        }
        __syncthreads();

        if (active) {
            for (int ci = 0; ci < cc; ci++) {
                const float* inC = in + ((size_t)(n * Cin + ci0 + ci)) * Hin * Win;
                const float* swp = sw + ci * 72;

                if (MODE == 1) {
                    float v[3][2 * PX + 1];
#pragma unroll
                    for (int dy = 0; dy < 3; dy++) {
                        int iy = 2 * oy + dy - 1;
                        bool rok = (iy >= 0) && (iy < Hin);
                        const float* row = inC + (size_t)max(iy, 0) * Win;
#pragma unroll
                        for (int j = 0; j < 2 * PX + 1; j++) {
                            int ix = 2 * ox0 - 1 + j;
                            v[dy][j] = (rok && ix >= 0 && ix < Win) ? __ldg(row + ix) : 0.f;
                        }
                    }
#pragma unroll
                    for (int dy = 0; dy < 3; dy++)
#pragma unroll
                        for (int dx = 0; dx < 3; dx++) {
                            const float* wk = swp + (dy * 3 + dx) * 8;
#pragma unroll
                            for (int p = 0; p < PX; p++) {
                                float val = v[dy][2 * p + dx];
#pragma unroll
                                for (int c = 0; c < 8; c++) acc[p][c] += val * wk[c];
                            }
                        }
                } else {
                    float v[3][PX + 2];
#pragma unroll
                    for (int dy = 0; dy < 3; dy++) {
                        int iy = oy + dy - 1;
                        bool rok = (iy >= 0) && (iy < Hin);
                        const float* row = inC + (size_t)max(iy, 0) * Win;
#pragma unroll
                        for (int j = 0; j < PX + 2; j++) {
                            int ix = ox0 - 1 + j;
                            v[dy][j] = (rok && ix >= 0 && ix < Win) ? __ldg(row + ix) : 0.f;
                        }
                    }
#pragma unroll
                    for (int dy = 0; dy < 3; dy++)
#pragma unroll
                        for (int dx = 0; dx < 3; dx++) {
                            const float* wk = swp + (dy * 3 + dx) * 8;
#pragma unroll
                            for (int p = 0; p < PX; p++) {
                                float val = v[dy][p + dx];
#pragma unroll
                                for (int c = 0; c < 8; c++) acc[p][c] += val * wk[c];
                            }
                        }
                }
            }
        }
    }

    if (!active) return;
#pragma unroll
    for (int c = 0; c < 8; c++) {
        float bb = bias[cob + c];
        float* outC = out + ((size_t)(n * Cout + cob + c) * Hout + oy) * Wout + ox0;
#pragma unroll
        for (int p = 0; p < PX; p++) {
            float r = acc[p][c] + bb;
            if (RELU) r = (r >= 0.f) ? r : LRELU_SLOPE * r;
            outC[p] = r;
        }
    }
}

// ---------------------------------------------------------------------------
// Decoder: zero-insert upsample (x2) + SAME 3x3 conv + LeakyReLU, via exact
// parity decomposition. For half-res site (y,x), the four outputs
//   out(2y,2x)     = w11*a
//   out(2y,2x+1)   = w10*a + w12*b
//   out(2y+1,2x)   = w01*a + w21*c
//   out(2y+1,2x+1) = w00*a + w02*b + w20*c + w22*d
// with a=in(y,x), b=in(y,x+1), c=in(y+1,x), d=in(y+1,x+1) use each of the 9
// weights exactly once -> same FLOPs as a half-res 3x3 conv (4x fewer than
// computing the upsampled conv directly). Input dims are the HALF-RES dims.
// Each thread: PX half-res x sites (=> 2*PX contiguous output cols, 2 rows),
// 8 output channels.
// ---------------------------------------------------------------------------
template<int PX, bool RELU>
__global__ void convT3x3_kernel(const float* __restrict__ in,
                                const float* __restrict__ wgt,
                                const float* __restrict__ bias,
                                float* __restrict__ out,
                                int N, int Cin, int Hh, int Wh, int Cout)
{
    __shared__ float sw[8 * 9 * 8];   // sw[ci][k][co],  k = dy*3+dx

    const int coChunks = Cout >> 3;
    const int z  = blockIdx.z;
    const int n  = z / coChunks;
    const int cob = (z - n * coChunks) << 3;

    const int y  = blockIdx.y * blockDim.y + threadIdx.y;          // half-res row
    const int x0 = (blockIdx.x * blockDim.x + threadIdx.x) * PX;   // half-res col
    const bool active = (y < Hh) && (x0 < Wh);

    // acc[row parity][output col within 2*PX][co]
    float acc[2][2 * PX][8];
#pragma unroll
    for (int r = 0; r < 2; r++)
#pragma unroll
        for (int p = 0; p < 2 * PX; p++)
#pragma unroll
            for (int c = 0; c < 8; c++) acc[r][p][c] = 0.f;

    const int tid = threadIdx.y * blockDim.x + threadIdx.x;
    const int nthreads = blockDim.x * blockDim.y;

    for (int ci0 = 0; ci0 < Cin; ci0 += 8) {
        __syncthreads();
        for (int e = tid; e < 8 * 9 * 8; e += nthreads) {
            int ci = e / 72;
            int r  = e - ci * 72;
            int k  = r >> 3;
            int co = r & 7;
            sw[e] = wgt[((size_t)(cob + co) * Cin + (ci0 + ci)) * 9 + k];
        }
        __syncthreads();

        if (active) {
#pragma unroll 4
            for (int ci = 0; ci < 8; ci++) {
                const float* inC = in + ((size_t)(n * Cin + ci0 + ci)) * Hh * Wh;
                const float* swp = sw + ci * 72;

                float v[2][PX + 1];
#pragma unroll
                for (int r = 0; r < 2; r++) {
                    int iy = y + r;
                    bool rok = (iy < Hh);
                    const float* row = inC + (size_t)min(iy, Hh - 1) * Wh;
#pragma unroll
                    for (int j = 0; j < PX + 1; j++) {
                        int ix = x0 + j;
                        v[r][j] = (rok && ix < Wh) ? __ldg(row + ix) : 0.f;
                    }
                }
#pragma unroll
                for (int p = 0; p < PX; p++) {
                    float a = v[0][p], b = v[0][p + 1];
                    float c_ = v[1][p], d = v[1][p + 1];
                    const float* w00 = swp + 0 * 8;
                    const float* w01 = swp + 1 * 8;
                    const float* w02 = swp + 2 * 8;
                    const float* w10 = swp + 3 * 8;
                    const float* w11 = swp + 4 * 8;
                    const float* w12 = swp + 5 * 8;
                    const float* w20 = swp + 6 * 8;
                    const float* w21 = swp + 7 * 8;
                    const float* w22 = swp + 8 * 8;
#pragma unroll
                    for (int c = 0; c < 8; c++) {
                        acc[0][2 * p    ][c] += w11[c] * a;
                        acc[0][2 * p + 1][c] += w10[c] * a + w12[c] * b;
                        acc[1][2 * p    ][c] += w01[c] * a + w21[c] * c_;
                        acc[1][2 * p + 1][c] += w00[c] * a + w02[c] * b
                                              + w20[c] * c_ + w22[c] * d;
                    }
                }
            }
        }
    }

    if (!active) return;
    const int Hout = 2 * Hh, Wout = 2 * Wh;
#pragma unroll
    for (int c = 0; c < 8; c++) {
        float bb = bias[cob + c];
#pragma unroll
        for (int r = 0; r < 2; r++) {
            float* outC = out + ((size_t)(n * Cout + cob + c) * Hout + (2 * y + r)) * Wout + 2 * x0;
#pragma unroll
            for (int p = 0; p < 2 * PX; p++) {
                if (2 * x0 + p >= Wout) break;
                float v = acc[r][p][c] + bb;
                if (RELU) v = (v >= 0.f) ? v : LRELU_SLOPE * v;
                outC[p] = v;
            }
        }
    }
}

// ---------------------------------------------------------------------------
// BatchNorm (training-mode batch stats over N,H,W) + LeakyReLU, in place.
// ---------------------------------------------------------------------------
__global__ void bn_lrelu_kernel(float* __restrict__ data,
                                const float* __restrict__ gamma,
                                const float* __restrict__ beta,
                                int N, int C, int HW)
{
    const int c = blockIdx.x;
    const int M = N * HW;
    __shared__ float red[64];

    float s = 0.f, q = 0.f;
    for (int i = threadIdx.x; i < M; i += blockDim.x) {
        int n = i / HW, p = i - n * HW;
        float v = data[((size_t)(n * C + c)) * HW + p];
        s += v; q += v * v;
    }
#pragma unroll
    for (int o = 16; o; o >>= 1) {
        s += __shfl_down_sync(0xFFFFFFFFu, s, o);
        q += __shfl_down_sync(0xFFFFFFFFu, q, o);
    }
    int wid = threadIdx.x >> 5, lid = threadIdx.x & 31;
    int nw = blockDim.x >> 5;
    if (lid == 0) { red[wid] = s; red[wid + 32] = q; }
    __syncthreads();
    if (wid == 0) {
        s = (lid < nw) ? red[lid] : 0.f;
        q = (lid < nw) ? red[lid + 32] : 0.f;
#pragma unroll
        for (int o = 16; o; o >>= 1) {
            s += __shfl_down_sync(0xFFFFFFFFu, s, o);
            q += __shfl_down_sync(0xFFFFFFFFu, q, o);
        }
        if (lid == 0) { red[0] = s; red[1] = q; }
    }
    __syncthreads();
    float mu  = red[0] / (float)M;
    float var = red[1] / (float)M - mu * mu;
    float sc  = gamma[c] * rsqrtf(var + BN_EPS);
    float sh  = beta[c] - mu * sc;
    for (int i = threadIdx.x; i < M; i += blockDim.x) {
        int n = i / HW, p = i - n * HW;
        size_t idx = ((size_t)(n * C + c)) * HW + p;
        float v = data[idx] * sc + sh;
        data[idx] = (v >= 0.f) ? v : LRELU_SLOPE * v;
    }
}

// ---------------------------------------------------------------------------
// 1x1 epilogue: out[n,o,hw] = sum_c in[n,c,hw] * w[o,c] + b[o],  o=3, c=64
// ---------------------------------------------------------------------------
__global__ void conv1x1_ep_kernel(const float* __restrict__ in,
                                  const float* __restrict__ w,
                                  const float* __restrict__ b,
                                  float* __restrict__ out,
                                  int N, int C, int HW)
{
    int p = blockIdx.x * blockDim.x + threadIdx.x;
    int total = N * HW;
    if (p >= total) return;
    int n = p / HW, q = p - n * HW;
    const float* base = in + (size_t)n * C * HW + q;
    float a0 = b[0], a1 = b[1], a2 = b[2];
#pragma unroll 8
    for (int c = 0; c < 64; c++) {
        float v = __ldg(base + (size_t)c * HW);
        a0 += v * w[c];
        a1 += v * w[64 + c];
        a2 += v * w[128 + c];
    }
    out[((size_t)(n * 3 + 0)) * HW + q] = a0;
    out[((size_t)(n * 3 + 1)) * HW + q] = a1;
    out[((size_t)(n * 3 + 2)) * HW + q] = a2;
}

// ---------------------------------------------------------------------------
// Host side
// ---------------------------------------------------------------------------
static void run_conv(int mode, bool relu,
                     const float* in, const float* w, const float* b, float* out,
                     int N, int Cin, int Hin, int Win, int Cout, int Hout, int Wout)
{
    int PXv, WG, YT;
    if (Wout >= 64)      { PXv = 4; WG = 16; YT = 16; }
    else if (Wout == 32) { PXv = 4; WG = 8;  YT = 32; }
    else                 { PXv = 1; WG = 16; YT = 16; }
    dim3 blk(WG, YT);
    dim3 grd((Wout + PXv * WG - 1) / (PXv * WG), (Hout + YT - 1) / YT, N * (Cout >> 3));

#define ARGS in, w, b, out, N, Cin, Hin, Win, Cout, Hout, Wout
    if (mode == 0) {
        if (PXv == 4) { if (relu) conv3x3_kernel<0,4,true ><<<grd,blk>>>(ARGS);
                        else      conv3x3_kernel<0,4,false><<<grd,blk>>>(ARGS); }
        else          { if (relu) conv3x3_kernel<0,1,true ><<<grd,blk>>>(ARGS);
                        else      conv3x3_kernel<0,1,false><<<grd,blk>>>(ARGS); }
    } else {
        if (PXv == 4) { if (relu) conv3x3_kernel<1,4,true ><<<grd,blk>>>(ARGS);
                        else      conv3x3_kernel<1,4,false><<<grd,blk>>>(ARGS); }
        else          { if (relu) conv3x3_kernel<1,1,true ><<<grd,blk>>>(ARGS);
                        else      conv3x3_kernel<1,1,false><<<grd,blk>>>(ARGS); }
    }
#undef ARGS
}

// Decoder launcher: in is half-res (Hh x Wh); out is (2Hh x 2Wh).
static void run_convT(const float* in, const float* w, const float* b, float* out,
                      int N, int Cin, int Hh, int Wh, int Cout)
{
    if (Wh >= 32) {
        const int PXv = 2;
        dim3 blk(16, 16);
        dim3 grd((Wh + PXv * 16 - 1) / (PXv * 16), (Hh + 15) / 16, N * (Cout >> 3));
        convT3x3_kernel<2, true><<<grd, blk>>>(in, w, b, out, N, Cin, Hh, Wh, Cout);
    } else {
        const int PXv = 1;
        dim3 blk(16, 16);
        dim3 grd((Wh + PXv * 16 - 1) / (PXv * 16), (Hh + 15) / 16, N * (Cout >> 3));
        convT3x3_kernel<1, true><<<grd, blk>>>(in, w, b, out, N, Cin, Hh, Wh, Cout);
    }
}

extern "C" void kernel_launch(void* const* d_in, const int* in_sizes, int n_in,
                              void* d_out, int out_size)
{
    (void)in_sizes; (void)n_in; (void)out_size;

    // metadata order:
    // 0:x 1:w_d0 2:b_d0 3:w_d1 4:b_d1 5:w_d2 6:b_d2 7:w_d3 8:b_d3 9:w_d4 10:b_d4
    // 11:w_in 12:b_in 13:gamma 14:beta
    // 15:w_u0 16:b_u0 17:w_u1 18:b_u1 19:w_u2 20:b_u2 21:w_u3 22:b_u3 23:w_u4 24:b_u4
    // 25:w_ep 26:b_ep
    const float* x = (const float*)d_in[0];
#define IN(i) ((const float*)d_in[(i)])

    void *pa, *pb;
    cudaGetSymbolAddress(&pa, g_bufA);
    cudaGetSymbolAddress(&pb, g_bufB);
    float* A = (float*)pa;
    float* B = (float*)pb;
    float* O = (float*)d_out;

    // ---- encoder (conv3x3 + lrelu, fused stride-2 output subsample) ----
    run_conv(1, true, x, IN(1),  IN(2),  A, 2,    3, 512, 512,   64, 256, 256);
    run_conv(1, true, A, IN(3),  IN(4),  B, 2,   64, 256, 256,  128, 128, 128);
    run_conv(1, true, B, IN(5),  IN(6),  A, 2,  128, 128, 128,  256,  64,  64);
    run_conv(1, true, A, IN(7),  IN(8),  B, 2,  256,  64,  64,  512,  32,  32);
    run_conv(1, true, B, IN(9),  IN(10), A, 2,  512,  32,  32, 1024,  16,  16);

    // ---- innermost: conv + BN(batch stats) + lrelu ----
    run_conv(0, false, A, IN(11), IN(12), B, 2, 1024, 16, 16, 1024, 16, 16);
    bn_lrelu_kernel<<<1024, 256>>>(B, IN(13), IN(14), 2, 1024, 16 * 16);

    // ---- decoder (parity-decomposed transposed conv + lrelu) ----
    run_convT(B, IN(15), IN(16), A, 2, 1024, 16, 16,    512);
    run_convT(A, IN(17), IN(18), B, 2,  512, 32, 32,    256);
    run_convT(B, IN(19), IN(20), A, 2,  256, 64, 64,    128);
    run_convT(A, IN(21), IN(22), B, 2,  128, 128, 128,   64);
    run_convT(B, IN(23), IN(24), A, 2,   64, 256, 256,   64);

    // ---- 1x1 epilogue ----
    int HW = 512 * 512;
    int total = 2 * HW;
    conv1x1_ep_kernel<<<(total + 255) / 256, 256>>>(A, IN(25), IN(26), O, 2, 64, HW);
#undef IN
}

// round 7
// speedup vs baseline: 1.2123x; 1.2123x over previous
#include <cuda_runtime.h>

#define LRELU_SLOPE 0.01f
#define BN_EPS 1e-5f

// Ping-pong scratch: max intermediate is 2*64*512*512 = 33,554,432 floats (134 MB).
__device__ float g_bufA[33554432];
__device__ float g_bufB[33554432];
// Split-K partial buffer: max SK*N*Cout*HW = 8.4M floats (u0@SK8, u1@SK4); 16M safe.
__device__ float g_bufC[16777216];

// ---------------------------------------------------------------------------
// Encoder / bottleneck 3x3 conv kernel.
//   MODE 0: plain SAME conv (Hin==Hout)
//   MODE 1: fused stride-2 subsample of conv output: out(oy,ox)=conv(in)(2oy,2ox)
// Split-K: gridDim.z = SK * N * (Cout/8); each kb-slice covers Cin/SK input
// channels. If SK>1, raw partials are written to out + kb*chunk (no bias/relu).
// ---------------------------------------------------------------------------
template<int MODE, int PX, bool RELU>
__global__ void conv3x3_kernel(const float* __restrict__ in,
                               const float* __restrict__ wgt,
                               const float* __restrict__ bias,
                               float* __restrict__ out,
                               int N, int Cin, int Hin, int Win,
                               int Cout, int Hout, int Wout, int SK)
{
    __shared__ float sw[8 * 9 * 8];   // sw[ci][k][co]

    const int coChunks = Cout >> 3;
    const int zPerK = N * coChunks;
    const int kb = blockIdx.z / zPerK;
    const int z  = blockIdx.z - kb * zPerK;
    const int n  = z / coChunks;
    const int cob = (z - n * coChunks) << 3;

    const int ciBegin = kb * (Cin / SK);
    const int ciEnd   = ciBegin + (Cin / SK);

    const int oy  = blockIdx.y * blockDim.y + threadIdx.y;
    const int ox0 = (blockIdx.x * blockDim.x + threadIdx.x) * PX;
    const bool active = (oy < Hout) && (ox0 < Wout);

    float acc[PX][8];
#pragma unroll
    for (int p = 0; p < PX; p++)
#pragma unroll
        for (int c = 0; c < 8; c++) acc[p][c] = 0.f;

    const int tid = threadIdx.y * blockDim.x + threadIdx.x;
    const int nthreads = blockDim.x * blockDim.y;

    for (int ci0 = ciBegin; ci0 < ciEnd; ci0 += 8) {
        const int cc = min(8, ciEnd - ci0);

        __syncthreads();
        // cooperative load of the weight chunk: sw[ci*72 + k*8 + co]
        for (int e = tid; e < 8 * 9 * 8; e += nthreads) {
            int ci = e / 72;
            int r  = e - ci * 72;
            int k  = r >> 3;
            int co = r & 7;
            float v = 0.f;
            if (ci < cc)
                v = wgt[((size_t)(cob + co) * Cin + (ci0 + ci)) * 9 + k];
            sw[e] = v;
        }
        __syncthreads();

        if (active) {
            for (int ci = 0; ci < cc; ci++) {
                const float* inC = in + ((size_t)(n * Cin + ci0 + ci)) * Hin * Win;
                const float* swp = sw + ci * 72;

                if (MODE == 1) {
                    float v[3][2 * PX + 1];
#pragma unroll
                    for (int dy = 0; dy < 3; dy++) {
                        int iy = 2 * oy + dy - 1;
                        bool rok = (iy >= 0) && (iy < Hin);
                        const float* row = inC + (size_t)max(iy, 0) * Win;
#pragma unroll
                        for (int j = 0; j < 2 * PX + 1; j++) {
                            int ix = 2 * ox0 - 1 + j;
                            v[dy][j] = (rok && ix >= 0 && ix < Win) ? __ldg(row + ix) : 0.f;
                        }
                    }
#pragma unroll
                    for (int dy = 0; dy < 3; dy++)
#pragma unroll
                        for (int dx = 0; dx < 3; dx++) {
                            const float* wk = swp + (dy * 3 + dx) * 8;
#pragma unroll
                            for (int p = 0; p < PX; p++) {
                                float val = v[dy][2 * p + dx];
#pragma unroll
                                for (int c = 0; c < 8; c++) acc[p][c] += val * wk[c];
                            }
                        }
                } else {
                    float v[3][PX + 2];
#pragma unroll
                    for (int dy = 0; dy < 3; dy++) {
                        int iy = oy + dy - 1;
                        bool rok = (iy >= 0) && (iy < Hin);
                        const float* row = inC + (size_t)max(iy, 0) * Win;
#pragma unroll
                        for (int j = 0; j < PX + 2; j++) {
                            int ix = ox0 - 1 + j;
                            v[dy][j] = (rok && ix >= 0 && ix < Win) ? __ldg(row + ix) : 0.f;
                        }
                    }
#pragma unroll
                    for (int dy = 0; dy < 3; dy++)
#pragma unroll
                        for (int dx = 0; dx < 3; dx++) {
                            const float* wk = swp + (dy * 3 + dx) * 8;
#pragma unroll
                            for (int p = 0; p < PX; p++) {
                                float val = v[dy][p + dx];
#pragma unroll
                                for (int c = 0; c < 8; c++) acc[p][c] += val * wk[c];
                            }
                        }
                }
            }
        }
    }

    if (!active) return;

    if (SK > 1) {
        // raw partial write (no bias / activation)
        const size_t chunk = (size_t)N * Cout * Hout * Wout;
        float* pout = out + (size_t)kb * chunk;
#pragma unroll
        for (int c = 0; c < 8; c++) {
            float* outC = pout + ((size_t)(n * Cout + cob + c) * Hout + oy) * Wout + ox0;
#pragma unroll
            for (int p = 0; p < PX; p++) outC[p] = acc[p][c];
        }
    } else {
#pragma unroll
        for (int c = 0; c < 8; c++) {
            float bb = bias[cob + c];
            float* outC = out + ((size_t)(n * Cout + cob + c) * Hout + oy) * Wout + ox0;
#pragma unroll
            for (int p = 0; p < PX; p++) {
                float r = acc[p][c] + bb;
                if (RELU) r = (r >= 0.f) ? r : LRELU_SLOPE * r;
                outC[p] = r;
            }
        }
    }
}

// ---------------------------------------------------------------------------
// Decoder: zero-insert upsample (x2) + SAME 3x3 conv + LeakyReLU via exact
// parity decomposition (each of the 9 weights used exactly once per half-res
// site -> 4x fewer FLOPs than direct conv on the upsampled grid).
// Split-K identical to above.
// ---------------------------------------------------------------------------
template<int PX, bool RELU>
__global__ void convT3x3_kernel(const float* __restrict__ in,
                                const float* __restrict__ wgt,
                                const float* __restrict__ bias,
                                float* __restrict__ out,
                                int N, int Cin, int Hh, int Wh, int Cout, int SK)
{
    __shared__ float sw[8 * 9 * 8];   // sw[ci][k][co],  k = dy*3+dx

    const int coChunks = Cout >> 3;
    const int zPerK = N * coChunks;
    const int kb = blockIdx.z / zPerK;
    const int z  = blockIdx.z - kb * zPerK;
    const int n  = z / coChunks;
    const int cob = (z - n * coChunks) << 3;

    const int ciBegin = kb * (Cin / SK);
    const int ciEnd   = ciBegin + (Cin / SK);

    const int y  = blockIdx.y * blockDim.y + threadIdx.y;          // half-res row
    const int x0 = (blockIdx.x * blockDim.x + threadIdx.x) * PX;   // half-res col
    const bool active = (y < Hh) && (x0 < Wh);

    float acc[2][2 * PX][8];
#pragma unroll
    for (int r = 0; r < 2; r++)
#pragma unroll
        for (int p = 0; p < 2 * PX; p++)
#pragma unroll
            for (int c = 0; c < 8; c++) acc[r][p][c] = 0.f;

    const int tid = threadIdx.y * blockDim.x + threadIdx.x;
    const int nthreads = blockDim.x * blockDim.y;

    for (int ci0 = ciBegin; ci0 < ciEnd; ci0 += 8) {
        __syncthreads();
        for (int e = tid; e < 8 * 9 * 8; e += nthreads) {
            int ci = e / 72;
            int r  = e - ci * 72;
            int k  = r >> 3;
            int co = r & 7;
            sw[e] = wgt[((size_t)(cob + co) * Cin + (ci0 + ci)) * 9 + k];
        }
        __syncthreads();

        if (active) {
#pragma unroll 4
            for (int ci = 0; ci < 8; ci++) {
                const float* inC = in + ((size_t)(n * Cin + ci0 + ci)) * Hh * Wh;
                const float* swp = sw + ci * 72;

                float v[2][PX + 1];
#pragma unroll
                for (int r = 0; r < 2; r++) {
                    int iy = y + r;
                    bool rok = (iy < Hh);
                    const float* row = inC + (size_t)min(iy, Hh - 1) * Wh;
#pragma unroll
                    for (int j = 0; j < PX + 1; j++) {
                        int ix = x0 + j;
                        v[r][j] = (rok && ix < Wh) ? __ldg(row + ix) : 0.f;
                    }
                }
#pragma unroll
                for (int p = 0; p < PX; p++) {
                    float a = v[0][p], b = v[0][p + 1];
                    float c_ = v[1][p], d = v[1][p + 1];
                    const float* w00 = swp + 0 * 8;
                    const float* w01 = swp + 1 * 8;
                    const float* w02 = swp + 2 * 8;
                    const float* w10 = swp + 3 * 8;
                    const float* w11 = swp + 4 * 8;
                    const float* w12 = swp + 5 * 8;
                    const float* w20 = swp + 6 * 8;
                    const float* w21 = swp + 7 * 8;
                    const float* w22 = swp + 8 * 8;
#pragma unroll
                    for (int c = 0; c < 8; c++) {
                        acc[0][2 * p    ][c] += w11[c] * a;
                        acc[0][2 * p + 1][c] += w10[c] * a + w12[c] * b;
                        acc[1][2 * p    ][c] += w01[c] * a + w21[c] * c_;
                        acc[1][2 * p + 1][c] += w00[c] * a + w02[c] * b
                                              + w20[c] * c_ + w22[c] * d;
                    }
                }
            }
        }
    }

    if (!active) return;
    const int Hout = 2 * Hh, Wout = 2 * Wh;

    if (SK > 1) {
        const size_t chunk = (size_t)N * Cout * Hout * Wout;
        float* pbase = out + (size_t)kb * chunk;
#pragma unroll
        for (int c = 0; c < 8; c++) {
#pragma unroll
            for (int r = 0; r < 2; r++) {
                float* outC = pbase + ((size_t)(n * Cout + cob + c) * Hout + (2 * y + r)) * Wout + 2 * x0;
#pragma unroll
                for (int p = 0; p < 2 * PX; p++) {
                    if (2 * x0 + p >= Wout) break;
                    outC[p] = acc[r][p][c];
                }
            }
        }
    } else {
#pragma unroll
        for (int c = 0; c < 8; c++) {
            float bb = bias[cob + c];
#pragma unroll
            for (int r = 0; r < 2; r++) {
                float* outC = out + ((size_t)(n * Cout + cob + c) * Hout + (2 * y + r)) * Wout + 2 * x0;
#pragma unroll
                for (int p = 0; p < 2 * PX; p++) {
                    if (2 * x0 + p >= Wout) break;
                    float v = acc[r][p][c] + bb;
                    if (RELU) v = (v >= 0.f) ? v : LRELU_SLOPE * v;
                    outC[p] = v;
                }
            }
        }
    }
}

// ---------------------------------------------------------------------------
// Split-K reduce + bias + optional LeakyReLU (float4 vectorized).
// part layout: [SK][N][Cout][HW]; out: [N][Cout][HW]. chunk % 4 == 0, HW % 4 == 0.
// ---------------------------------------------------------------------------
__global__ void reduce_bias_act_kernel(const float* __restrict__ part,
                                       const float* __restrict__ bias,
                                       float* __restrict__ out,
                                       int SK, size_t chunk4, int HW4, int Cout, int relu)
{
    size_t i = (size_t)blockIdx.x * blockDim.x + threadIdx.x;   // float4 index
    if (i >= chunk4) return;
    const float4* p4 = (const float4*)part;
    float4 s = p4[i];
    for (int k = 1; k < SK; k++) {
        float4 t = p4[(size_t)k * chunk4 + i];
        s.x += t.x; s.y += t.y; s.z += t.z; s.w += t.w;
    }
    int c = (int)((i / HW4) % Cout);
    float bb = bias[c];
    s.x += bb; s.y += bb; s.z += bb; s.w += bb;
    if (relu) {
        s.x = (s.x >= 0.f) ? s.x : LRELU_SLOPE * s.x;
        s.y = (s.y >= 0.f) ? s.y : LRELU_SLOPE * s.y;
        s.z = (s.z >= 0.f) ? s.z : LRELU_SLOPE * s.z;
        s.w = (s.w >= 0.f) ? s.w : LRELU_SLOPE * s.w;
    }
    ((float4*)out)[i] = s;
}

// ---------------------------------------------------------------------------
// BatchNorm (training-mode batch stats over N,H,W) + LeakyReLU, in place.
// ---------------------------------------------------------------------------
__global__ void bn_lrelu_kernel(float* __restrict__ data,
                                const float* __restrict__ gamma,
                                const float* __restrict__ beta,
                                int N, int C, int HW)
{
    const int c = blockIdx.x;
    const int M = N * HW;
    __shared__ float red[64];

    float s = 0.f, q = 0.f;
    for (int i = threadIdx.x; i < M; i += blockDim.x) {
        int n = i / HW, p = i - n * HW;
        float v = data[((size_t)(n * C + c)) * HW + p];
        s += v; q += v * v;
    }
#pragma unroll
    for (int o = 16; o; o >>= 1) {
        s += __shfl_down_sync(0xFFFFFFFFu, s, o);
        q += __shfl_down_sync(0xFFFFFFFFu, q, o);
    }
    int wid = threadIdx.x >> 5, lid = threadIdx.x & 31;
    int nw = blockDim.x >> 5;
    if (lid == 0) { red[wid] = s; red[wid + 32] = q; }
    __syncthreads();
    if (wid == 0) {
        s = (lid < nw) ? red[lid] : 0.f;
        q = (lid < nw) ? red[lid + 32] : 0.f;
#pragma unroll
        for (int o = 16; o; o >>= 1) {
            s += __shfl_down_sync(0xFFFFFFFFu, s, o);
            q += __shfl_down_sync(0xFFFFFFFFu, q, o);
        }
        if (lid == 0) { red[0] = s; red[1] = q; }
    }
    __syncthreads();
    float mu  = red[0] / (float)M;
    float var = red[1] / (float)M - mu * mu;
    float sc  = gamma[c] * rsqrtf(var + BN_EPS);
    float sh  = beta[c] - mu * sc;
    for (int i = threadIdx.x; i < M; i += blockDim.x) {
        int n = i / HW, p = i - n * HW;
        size_t idx = ((size_t)(n * C + c)) * HW + p;
        float v = data[idx] * sc + sh;
        data[idx] = (v >= 0.f) ? v : LRELU_SLOPE * v;
    }
}

// ---------------------------------------------------------------------------
// 1x1 epilogue: out[n,o,hw] = sum_c in[n,c,hw] * w[o,c] + b[o],  o=3, c=64
// ---------------------------------------------------------------------------
__global__ void conv1x1_ep_kernel(const float* __restrict__ in,
                                  const float* __restrict__ w,
                                  const float* __restrict__ b,
                                  float* __restrict__ out,
                                  int N, int C, int HW)
{
    int p = blockIdx.x * blockDim.x + threadIdx.x;
    int total = N * HW;
    if (p >= total) return;
    int n = p / HW, q = p - n * HW;
    const float* base = in + (size_t)n * C * HW + q;
    float a0 = b[0], a1 = b[1], a2 = b[2];
#pragma unroll 8
    for (int c = 0; c < 64; c++) {
        float v = __ldg(base + (size_t)c * HW);
        a0 += v * w[c];
        a1 += v * w[64 + c];
        a2 += v * w[128 + c];
    }
    out[((size_t)(n * 3 + 0)) * HW + q] = a0;
    out[((size_t)(n * 3 + 1)) * HW + q] = a1;
    out[((size_t)(n * 3 + 2)) * HW + q] = a2;
}

// ---------------------------------------------------------------------------
// Host side
// ---------------------------------------------------------------------------
static float* g_partial = nullptr;

static void run_reduce(const float* b, float* out, int sk, int N, int Cout,
                       int Hout, int Wout, bool relu)
{
    size_t chunk4 = ((size_t)N * Cout * Hout * Wout) >> 2;
    int threads = 256;
    int blocks = (int)((chunk4 + threads - 1) / threads);
    reduce_bias_act_kernel<<<blocks, threads>>>(g_partial, b, out, sk, chunk4,
                                                (Hout * Wout) >> 2, Cout, relu ? 1 : 0);
}

static void run_conv(int mode, bool relu, int sk,
                     const float* in, const float* w, const float* b, float* out,
                     int N, int Cin, int Hin, int Win, int Cout, int Hout, int Wout)
{
    int PXv, WG, YT;
    if (Wout >= 64)      { PXv = 4; WG = 16; YT = 16; }
    else if (Wout == 32) { PXv = 4; WG = 8;  YT = 32; }
    else                 { PXv = 2; WG = 8;  YT = 16; }   // 16x16 layers: 128 thr
    dim3 blk(WG, YT);
    dim3 grd((Wout + PXv * WG - 1) / (PXv * WG), (Hout + YT - 1) / YT,
             sk * N * (Cout >> 3));

    float* dst = (sk > 1) ? g_partial : out;

#define ARGS in, w, b, dst, N, Cin, Hin, Win, Cout, Hout, Wout, sk
    if (mode == 0) {
        if      (PXv == 4) conv3x3_kernel<0,4,false><<<grd,blk>>>(ARGS);
        else if (PXv == 2) conv3x3_kernel<0,2,false><<<grd,blk>>>(ARGS);
        else               conv3x3_kernel<0,1,false><<<grd,blk>>>(ARGS);
    } else {
        if      (PXv == 4) { if (relu && sk == 1) conv3x3_kernel<1,4,true ><<<grd,blk>>>(ARGS);
                             else                 conv3x3_kernel<1,4,false><<<grd,blk>>>(ARGS); }
        else if (PXv == 2) { if (relu && sk == 1) conv3x3_kernel<1,2,true ><<<grd,blk>>>(ARGS);
                             else                 conv3x3_kernel<1,2,false><<<grd,blk>>>(ARGS); }
        else               { if (relu && sk == 1) conv3x3_kernel<1,1,true ><<<grd,blk>>>(ARGS);
                             else                 conv3x3_kernel<1,1,false><<<grd,blk>>>(ARGS); }
    }
#undef ARGS

    if (sk > 1) run_reduce(b, out, sk, N, Cout, Hout, Wout, relu);
}

// Decoder launcher: in is half-res (Hh x Wh); out is (2Hh x 2Wh).
static void run_convT(int sk, const float* in, const float* w, const float* b, float* out,
                      int N, int Cin, int Hh, int Wh, int Cout)
{
    const int PXv = 2;
    int WG = (Wh >= 32) ? 16 : 8;
    dim3 blk(WG, 16);
    dim3 grd((Wh + PXv * WG - 1) / (PXv * WG), (Hh + 15) / 16, sk * N * (Cout >> 3));

    float* dst = (sk > 1) ? g_partial : out;
    if (sk == 1)
        convT3x3_kernel<2, true ><<<grd, blk>>>(in, w, b, dst, N, Cin, Hh, Wh, Cout, sk);
    else
        convT3x3_kernel<2, false><<<grd, blk>>>(in, w, b, dst, N, Cin, Hh, Wh, Cout, sk);

    if (sk > 1) run_reduce(b, out, sk, N, Cout, 2 * Hh, 2 * Wh, true);
}

extern "C" void kernel_launch(void* const* d_in, const int* in_sizes, int n_in,
                              void* d_out, int out_size)
{
    (void)in_sizes; (void)n_in; (void)out_size;

    const float* x = (const float*)d_in[0];
#define IN(i) ((const float*)d_in[(i)])

    void *pa, *pb, *pc;
    cudaGetSymbolAddress(&pa, g_bufA);
    cudaGetSymbolAddress(&pb, g_bufB);
    cudaGetSymbolAddress(&pc, g_bufC);
    float* A = (float*)pa;
    float* B = (float*)pb;
    g_partial = (float*)pc;
    float* O = (float*)d_out;

    // ---- encoder (conv3x3 + lrelu, fused stride-2 output subsample) ----
    run_conv(1, true, 1, x, IN(1),  IN(2),  A, 2,    3, 512, 512,   64, 256, 256);
    run_conv(1, true, 1, A, IN(3),  IN(4),  B, 2,   64, 256, 256,  128, 128, 128);
    run_conv(1, true, 2, B, IN(5),  IN(6),  A, 2,  128, 128, 128,  256,  64,  64);
    run_conv(1, true, 4, A, IN(7),  IN(8),  B, 2,  256,  64,  64,  512,  32,  32);
    run_conv(1, true, 4, B, IN(9),  IN(10), A, 2,  512,  32,  32, 1024,  16,  16);

    // ---- innermost: conv + BN(batch stats) + lrelu ----
    run_conv(0, false, 4, A, IN(11), IN(12), B, 2, 1024, 16, 16, 1024, 16, 16);
    bn_lrelu_kernel<<<1024, 256>>>(B, IN(13), IN(14), 2, 1024, 16 * 16);

    // ---- decoder (parity-decomposed transposed conv + lrelu) ----
    run_convT(8, B, IN(15), IN(16), A, 2, 1024, 16, 16,    512);
    run_convT(4, A, IN(17), IN(18), B, 2,  512, 32, 32,    256);
    run_convT(2, B, IN(19), IN(20), A, 2,  256, 64, 64,    128);
    run_convT(1, A, IN(21), IN(22), B, 2,  128, 128, 128,   64);
    run_convT(1, B, IN(23), IN(24), A, 2,   64, 256, 256,   64);

    // ---- 1x1 epilogue ----
    int HW = 512 * 512;
    int total = 2 * HW;
    conv1x1_ep_kernel<<<(total + 255) / 256, 256>>>(A, IN(25), IN(26), O, 2, 64, HW);
#undef IN
}

// round 12
// speedup vs baseline: 1.3033x; 1.0750x over previous
#include <cuda_runtime.h>

#define LRELU_SLOPE 0.01f
#define BN_EPS 1e-5f

// Ping-pong scratch: max intermediate is 2*64*512*512 = 33,554,432 floats (134 MB).
__device__ __align__(16) float g_bufA[33554432];
__device__ __align__(16) float g_bufB[33554432];
// Split-K partial buffer: max SK*N*Cout*HW = 8.4M floats (u0@SK8, u1@SK4); 16M safe.
__device__ __align__(16) float g_bufC[16777216];

__device__ __forceinline__ float lrelu(float v) {
    return (v >= 0.f) ? v : LRELU_SLOPE * v;
}

// ---------------------------------------------------------------------------
// Encoder / bottleneck 3x3 conv kernel.
//   MODE 0: plain SAME conv (Hin==Hout)
//   MODE 1: fused stride-2 subsample of conv output: out(oy,ox)=conv(in)(2oy,2ox)
// Split-K: gridDim.z = SK * N * (Cout/8); each kb-slice covers Cin/SK input
// channels. If SK>1, raw partials are written to out + kb*chunk (no bias/relu).
// MODE 1 interior threads use float4 loads (3 LDG/row instead of 9).
// Stores are float4/float2 vectorized (all launches are tail-free + aligned).
// ---------------------------------------------------------------------------
template<int MODE, int PX, bool RELU>
__global__ void conv3x3_kernel(const float* __restrict__ in,
                               const float* __restrict__ wgt,
                               const float* __restrict__ bias,
                               float* __restrict__ out,
                               int N, int Cin, int Hin, int Win,
                               int Cout, int Hout, int Wout, int SK)
{
    __shared__ float sw[8 * 9 * 8];   // sw[ci][k][co]

    const int coChunks = Cout >> 3;
    const int zPerK = N * coChunks;
    const int kb = blockIdx.z / zPerK;
    const int z  = blockIdx.z - kb * zPerK;
    const int n  = z / coChunks;
    const int cob = (z - n * coChunks) << 3;

    const int ciBegin = kb * (Cin / SK);
    const int ciEnd   = ciBegin + (Cin / SK);

    const int oy  = blockIdx.y * blockDim.y + threadIdx.y;
    const int ox0 = (blockIdx.x * blockDim.x + threadIdx.x) * PX;
    const bool active = (oy < Hout) && (ox0 < Wout);

    float acc[PX][8];
#pragma unroll
    for (int p = 0; p < PX; p++)
#pragma unroll
        for (int c = 0; c < 8; c++) acc[p][c] = 0.f;

    const int tid = threadIdx.y * blockDim.x + threadIdx.x;
    const int nthreads = blockDim.x * blockDim.y;

    for (int ci0 = ciBegin; ci0 < ciEnd; ci0 += 8) {
        const int cc = min(8, ciEnd - ci0);

        __syncthreads();
        // cooperative load of the weight chunk: sw[ci*72 + k*8 + co]
        for (int e = tid; e < 8 * 9 * 8; e += nthreads) {
            int ci = e / 72;
            int r  = e - ci * 72;
            int k  = r >> 3;
            int co = r & 7;
            float v = 0.f;
            if (ci < cc)
                v = wgt[((size_t)(cob + co) * Cin + (ci0 + ci)) * 9 + k];
            sw[e] = v;
        }
        __syncthreads();

        if (active) {
            for (int ci = 0; ci < cc; ci++) {
                const float* inC = in + ((size_t)(n * Cin + ci0 + ci)) * Hin * Win;
                const float* swp = sw + ci * 72;

                if (MODE == 1) {
                    float v[3][2 * PX + 1];
                    constexpr int NV4 = (2 * PX) / 4;   // float4 loads on fast path
                    const int bx = 2 * ox0;
#pragma unroll
                    for (int dy = 0; dy < 3; dy++) {
                        int iy = 2 * oy + dy - 1;
                        bool rok = (iy >= 0) && (iy < Hin);
                        const float* row = inC + (size_t)max(iy, 0) * Win;
                        if (!rok) {
#pragma unroll
                            for (int j = 0; j < 2 * PX + 1; j++) v[dy][j] = 0.f;
                        } else if (NV4 > 0 && ox0 > 0) {
                            // interior: [bx-1 .. bx+2*PX-1]; bx 16B-aligned,
                            // right edge always in-bounds (bx+2PX-1 <= Win-1).
                            const float* rp = row + bx;
                            v[dy][0] = rp[-1];
#pragma unroll
                            for (int k = 0; k < NV4; k++) {
                                float4 q = *(const float4*)(rp + 4 * k);
                                v[dy][4 * k + 1] = q.x;
                                v[dy][4 * k + 2] = q.y;
                                v[dy][4 * k + 3] = q.z;
                                v[dy][4 * k + 4] = q.w;
                            }
                        } else {
#pragma unroll
                            for (int j = 0; j < 2 * PX + 1; j++) {
                                int ix = bx - 1 + j;
                                v[dy][j] = (ix >= 0 && ix < Win) ? __ldg(row + ix) : 0.f;
                            }
                        }
                    }
#pragma unroll
                    for (int dy = 0; dy < 3; dy++)
#pragma unroll
                        for (int dx = 0; dx < 3; dx++) {
                            const float* wk = swp + (dy * 3 + dx) * 8;
#pragma unroll
                            for (int p = 0; p < PX; p++) {
                                float val = v[dy][2 * p + dx];
#pragma unroll
                                for (int c = 0; c < 8; c++) acc[p][c] += val * wk[c];
                            }
                        }
                } else {
                    float v[3][PX + 2];
#pragma unroll
                    for (int dy = 0; dy < 3; dy++) {
                        int iy = oy + dy - 1;
                        bool rok = (iy >= 0) && (iy < Hin);
                        const float* row = inC + (size_t)max(iy, 0) * Win;
#pragma unroll
                        for (int j = 0; j < PX + 2; j++) {
                            int ix = ox0 - 1 + j;
                            v[dy][j] = (rok && ix >= 0 && ix < Win) ? __ldg(row + ix) : 0.f;
                        }
                    }
#pragma unroll
                    for (int dy = 0; dy < 3; dy++)
#pragma unroll
                        for (int dx = 0; dx < 3; dx++) {
                            const float* wk = swp + (dy * 3 + dx) * 8;
#pragma unroll
                            for (int p = 0; p < PX; p++) {
                                float val = v[dy][p + dx];
#pragma unroll
                                for (int c = 0; c < 8; c++) acc[p][c] += val * wk[c];
                            }
                        }
                }
            }
        }
    }

    if (!active) return;

    // Vectorized stores. All launches guarantee Wout % (PX*blockDim.x) == 0
    // (no tail) and 16B-aligned rows, so PX=4 -> one float4, PX=2 -> one float2.
    const size_t chunk = (size_t)N * Cout * Hout * Wout;
    float* pout = (SK > 1) ? (out + (size_t)kb * chunk) : out;
#pragma unroll
    for (int c = 0; c < 8; c++) {
        float bb = (SK > 1) ? 0.f : bias[cob + c];
        float* outC = pout + ((size_t)(n * Cout + cob + c) * Hout + oy) * Wout + ox0;
        float r[PX];
#pragma unroll
        for (int p = 0; p < PX; p++) {
            r[p] = acc[p][c] + bb;
            if (RELU && SK == 1) r[p] = lrelu(r[p]);
        }
        if (PX == 4)      *(float4*)outC = make_float4(r[0], r[1], r[2], r[3]);
        else if (PX == 2) *(float2*)outC = make_float2(r[0], r[1]);
        else              outC[0] = r[0];
    }
}

// ---------------------------------------------------------------------------
// Decoder: zero-insert upsample (x2) + SAME 3x3 conv + LeakyReLU via exact
// parity decomposition (each of the 9 weights used exactly once per half-res
// site -> 4x fewer FLOPs than direct conv on the upsampled grid).
// Split-K identical to above. Stores are float4 (2*PX=4 contiguous, aligned,
// tail-free since Wh % PX == 0 for every layer).
// ---------------------------------------------------------------------------
template<int PX, bool RELU>
__global__ void convT3x3_kernel(const float* __restrict__ in,
                                const float* __restrict__ wgt,
                                const float* __restrict__ bias,
                                float* __restrict__ out,
                                int N, int Cin, int Hh, int Wh, int Cout, int SK)
{
    __shared__ float sw[8 * 9 * 8];   // sw[ci][k][co],  k = dy*3+dx

    const int coChunks = Cout >> 3;
    const int zPerK = N * coChunks;
    const int kb = blockIdx.z / zPerK;
    const int z  = blockIdx.z - kb * zPerK;
    const int n  = z / coChunks;
    const int cob = (z - n * coChunks) << 3;

    const int ciBegin = kb * (Cin / SK);
    const int ciEnd   = ciBegin + (Cin / SK);

    const int y  = blockIdx.y * blockDim.y + threadIdx.y;          // half-res row
    const int x0 = (blockIdx.x * blockDim.x + threadIdx.x) * PX;   // half-res col
    const bool active = (y < Hh) && (x0 < Wh);

    float acc[2][2 * PX][8];
#pragma unroll
    for (int r = 0; r < 2; r++)
#pragma unroll
        for (int p = 0; p < 2 * PX; p++)
#pragma unroll
            for (int c = 0; c < 8; c++) acc[r][p][c] = 0.f;

    const int tid = threadIdx.y * blockDim.x + threadIdx.x;
    const int nthreads = blockDim.x * blockDim.y;

    for (int ci0 = ciBegin; ci0 < ciEnd; ci0 += 8) {
        __syncthreads();
        for (int e = tid; e < 8 * 9 * 8; e += nthreads) {
            int ci = e / 72;
            int r  = e - ci * 72;
            int k  = r >> 3;
            int co = r & 7;
            sw[e] = wgt[((size_t)(cob + co) * Cin + (ci0 + ci)) * 9 + k];
        }
        __syncthreads();

        if (active) {
#pragma unroll 4
            for (int ci = 0; ci < 8; ci++) {
                const float* inC = in + ((size_t)(n * Cin + ci0 + ci)) * Hh * Wh;
                const float* swp = sw + ci * 72;

                float v[2][PX + 1];
#pragma unroll
                for (int r = 0; r < 2; r++) {
                    int iy = y + r;
                    bool rok = (iy < Hh);
                    const float* row = inC + (size_t)min(iy, Hh - 1) * Wh;
#pragma unroll
                    for (int j = 0; j < PX + 1; j++) {
                        int ix = x0 + j;
                        v[r][j] = (rok && ix < Wh) ? __ldg(row + ix) : 0.f;
                    }
                }
#pragma unroll
                for (int p = 0; p < PX; p++) {
                    float a = v[0][p], b = v[0][p + 1];
                    float c_ = v[1][p], d = v[1][p + 1];
                    const float* w00 = swp + 0 * 8;
                    const float* w01 = swp + 1 * 8;
                    const float* w02 = swp + 2 * 8;
                    const float* w10 = swp + 3 * 8;
                    const float* w11 = swp + 4 * 8;
                    const float* w12 = swp + 5 * 8;
                    const float* w20 = swp + 6 * 8;
                    const float* w21 = swp + 7 * 8;
                    const float* w22 = swp + 8 * 8;
#pragma unroll
                    for (int c = 0; c < 8; c++) {
                        acc[0][2 * p    ][c] += w11[c] * a;
                        acc[0][2 * p + 1][c] += w10[c] * a + w12[c] * b;
                        acc[1][2 * p    ][c] += w01[c] * a + w21[c] * c_;
                        acc[1][2 * p + 1][c] += w00[c] * a + w02[c] * b
                                              + w20[c] * c_ + w22[c] * d;
                    }
                }
            }
        }
    }

    if (!active) return;
    const int Hout = 2 * Hh, Wout = 2 * Wh;

    const size_t chunk = (size_t)N * Cout * Hout * Wout;
    float* pbase = (SK > 1) ? (out + (size_t)kb * chunk) : out;
#pragma unroll
    for (int c = 0; c < 8; c++) {
        float bb = (SK > 1) ? 0.f : bias[cob + c];
#pragma unroll
        for (int r = 0; r < 2; r++) {
            float* outC = pbase + ((size_t)(n * Cout + cob + c) * Hout + (2 * y + r)) * Wout + 2 * x0;
            float t[2 * PX];
#pragma unroll
            for (int p = 0; p < 2 * PX; p++) {
                t[p] = acc[r][p][c] + bb;
                if (RELU && SK == 1) t[p] = lrelu(t[p]);
            }
            if (2 * PX == 4) *(float4*)outC = make_float4(t[0], t[1], t[2], t[3]);
            else {
#pragma unroll
                for (int p = 0; p < 2 * PX; p++) outC[p] = t[p];
            }
        }
    }
}

// ---------------------------------------------------------------------------
// Split-K reduce + bias + optional LeakyReLU (float4 vectorized).
// part layout: [SK][N][Cout][HW]; out: [N][Cout][HW]. chunk % 4 == 0, HW % 4 == 0.
// ---------------------------------------------------------------------------
__global__ void reduce_bias_act_kernel(const float* __restrict__ part,
                                       const float* __restrict__ bias,
                                       float* __restrict__ out,
                                       int SK, size_t chunk4, int HW4, int Cout, int relu)
{
    size_t i = (size_t)blockIdx.x * blockDim.x + threadIdx.x;   // float4 index
    if (i >= chunk4) return;
    const float4* p4 = (const float4*)part;
    float4 s = p4[i];
    for (int k = 1; k < SK; k++) {
        float4 t = p4[(size_t)k * chunk4 + i];
        s.x += t.x; s.y += t.y; s.z += t.z; s.w += t.w;
    }
    int c = (int)((i / HW4) % Cout);
    float bb = bias[c];
    s.x += bb; s.y += bb; s.z += bb; s.w += bb;
    if (relu) {
        s.x = lrelu(s.x); s.y = lrelu(s.y); s.z = lrelu(s.z); s.w = lrelu(s.w);
    }
    ((float4*)out)[i] = s;
}

// ---------------------------------------------------------------------------
// BatchNorm (training-mode batch stats over N,H,W) + LeakyReLU, in place.
// ---------------------------------------------------------------------------
__global__ void bn_lrelu_kernel(float* __restrict__ data,
                                const float* __restrict__ gamma,
                                const float* __restrict__ beta,
                                int N, int C, int HW)
{
    const int c = blockIdx.x;
    const int M = N * HW;
    __shared__ float red[64];

    float s = 0.f, q = 0.f;
    for (int i = threadIdx.x; i < M; i += blockDim.x) {
        int n = i / HW, p = i - n * HW;
        float v = data[((size_t)(n * C + c)) * HW + p];
        s += v; q += v * v;
    }
#pragma unroll
    for (int o = 16; o; o >>= 1) {
        s += __shfl_down_sync(0xFFFFFFFFu, s, o);
        q += __shfl_down_sync(0xFFFFFFFFu, q, o);
    }
    int wid = threadIdx.x >> 5, lid = threadIdx.x & 31;
    int nw = blockDim.x >> 5;
    if (lid == 0) { red[wid] = s; red[wid + 32] = q; }
    __syncthreads();
    if (wid == 0) {
        s = (lid < nw) ? red[lid] : 0.f;
        q = (lid < nw) ? red[lid + 32] : 0.f;
#pragma unroll
        for (int o = 16; o; o >>= 1) {
            s += __shfl_down_sync(0xFFFFFFFFu, s, o);
            q += __shfl_down_sync(0xFFFFFFFFu, q, o);
        }
        if (lid == 0) { red[0] = s; red[1] = q; }
    }
    __syncthreads();
    float mu  = red[0] / (float)M;
    float var = red[1] / (float)M - mu * mu;
    float sc  = gamma[c] * rsqrtf(var + BN_EPS);
    float sh  = beta[c] - mu * sc;
    for (int i = threadIdx.x; i < M; i += blockDim.x) {
        int n = i / HW, p = i - n * HW;
        size_t idx = ((size_t)(n * C + c)) * HW + p;
        float v = data[idx] * sc + sh;
        data[idx] = (v >= 0.f) ? v : LRELU_SLOPE * v;
    }
}

// ---------------------------------------------------------------------------
// 1x1 epilogue (float4 over hw): out[n,o,hw] = sum_c in[n,c,hw]*w[o,c] + b[o]
// o=3, c=64. HW % 4 == 0; each thread does 4 consecutive hw positions.
// ---------------------------------------------------------------------------
__global__ void conv1x1_ep_kernel(const float* __restrict__ in,
                                  const float* __restrict__ w,
                                  const float* __restrict__ b,
                                  float* __restrict__ out,
                                  int N, int C, int HW)
{
    int HW4 = HW >> 2;
    int p = blockIdx.x * blockDim.x + threadIdx.x;   // float4 index
    int total4 = N * HW4;
    if (p >= total4) return;
    int n = p / HW4, q4 = p - n * HW4;
    const float4* base = (const float4*)(in + (size_t)n * C * HW) + q4;
    float4 a0 = make_float4(b[0], b[0], b[0], b[0]);
    float4 a1 = make_float4(b[1], b[1], b[1], b[1]);
    float4 a2 = make_float4(b[2], b[2], b[2], b[2]);
#pragma unroll 8
    for (int c = 0; c < 64; c++) {
        float4 v = __ldg(base + (size_t)c * HW4);
        float w0 = w[c], w1 = w[64 + c], w2 = w[128 + c];
        a0.x += v.x * w0; a0.y += v.y * w0; a0.z += v.z * w0; a0.w += v.w * w0;
        a1.x += v.x * w1; a1.y += v.y * w1; a1.z += v.z * w1; a1.w += v.w * w1;
        a2.x += v.x * w2; a2.y += v.y * w2; a2.z += v.z * w2; a2.w += v.w * w2;
    }
    float4* ob = (float4*)(out + (size_t)n * 3 * HW);
    ob[0 * HW4 + q4] = a0;
    ob[1 * HW4 + q4] = a1;
    ob[2 * HW4 + q4] = a2;
}

// ---------------------------------------------------------------------------
// Host side
// ---------------------------------------------------------------------------
static float* g_partial = nullptr;

static void run_reduce(const float* b, float* out, int sk, int N, int Cout,
                       int Hout, int Wout, bool relu)
{
    size_t chunk4 = ((size_t)N * Cout * Hout * Wout) >> 2;
    int threads = 256;
    int blocks = (int)((chunk4 + threads - 1) / threads);
    reduce_bias_act_kernel<<<blocks, threads>>>(g_partial, b, out, sk, chunk4,
                                                (Hout * Wout) >> 2, Cout, relu ? 1 : 0);
}

static void run_conv(int mode, bool relu, int sk,
                     const float* in, const float* w, const float* b, float* out,
                     int N, int Cin, int Hin, int Win, int Cout, int Hout, int Wout)
{
    int PXv, WG, YT;
    if (Wout >= 64)      { PXv = 4; WG = 16; YT = 16; }
    else if (Wout == 32) { PXv = 4; WG = 8;  YT = 32; }
    else                 { PXv = 2; WG = 8;  YT = 16; }   // 16x16 layers: 128 thr
    dim3 blk(WG, YT);
    dim3 grd((Wout + PXv * WG - 1) / (PXv * WG), (Hout + YT - 1) / YT,
             sk * N * (Cout >> 3));

    float* dst = (sk > 1) ? g_partial : out;

#define ARGS in, w, b, dst, N, Cin, Hin, Win, Cout, Hout, Wout, sk
    if (mode == 0) {
        if      (PXv == 4) conv3x3_kernel<0,4,false><<<grd,blk>>>(ARGS);
        else if (PXv == 2) conv3x3_kernel<0,2,false><<<grd,blk>>>(ARGS);
        else               conv3x3_kernel<0,1,false><<<grd,blk>>>(ARGS);
    } else {
        if      (PXv == 4) { if (relu && sk == 1) conv3x3_kernel<1,4,true ><<<grd,blk>>>(ARGS);
                             else                 conv3x3_kernel<1,4,false><<<grd,blk>>>(ARGS); }
        else if (PXv == 2) { if (relu && sk == 1) conv3x3_kernel<1,2,true ><<<grd,blk>>>(ARGS);
                             else                 conv3x3_kernel<1,2,false><<<grd,blk>>>(ARGS); }
        else               { if (relu && sk == 1) conv3x3_kernel<1,1,true ><<<grd,blk>>>(ARGS);
                             else                 conv3x3_kernel<1,1,false><<<grd,blk>>>(ARGS); }
    }
#undef ARGS

    if (sk > 1) run_reduce(b, out, sk, N, Cout, Hout, Wout, relu);
}

// Decoder launcher: in is half-res (Hh x Wh); out is (2Hh x 2Wh).
static void run_convT(int sk, const float* in, const float* w, const float* b, float* out,
                      int N, int Cin, int Hh, int Wh, int Cout)
{
    const int PXv = 2;
    int WG = (Wh >= 32) ? 16 : 8;
    dim3 blk(WG, 16);
    dim3 grd((Wh + PXv * WG - 1) / (PXv * WG), (Hh + 15) / 16, sk * N * (Cout >> 3));

    float* dst = (sk > 1) ? g_partial : out;
    if (sk == 1)
        convT3x3_kernel<2, true ><<<grd, blk>>>(in, w, b, dst, N, Cin, Hh, Wh, Cout, sk);
    else
        convT3x3_kernel<2, false><<<grd, blk>>>(in, w, b, dst, N, Cin, Hh, Wh, Cout, sk);

    if (sk > 1) run_reduce(b, out, sk, N, Cout, 2 * Hh, 2 * Wh, true);
}

extern "C" void kernel_launch(void* const* d_in, const int* in_sizes, int n_in,
                              void* d_out, int out_size)
{
    (void)in_sizes; (void)n_in; (void)out_size;

    const float* x = (const float*)d_in[0];
#define IN(i) ((const float*)d_in[(i)])

    void *pa, *pb, *pc;
    cudaGetSymbolAddress(&pa, g_bufA);
    cudaGetSymbolAddress(&pb, g_bufB);
    cudaGetSymbolAddress(&pc, g_bufC);
    float* A = (float*)pa;
    float* B = (float*)pb;
    g_partial = (float*)pc;
    float* O = (float*)d_out;

    // ---- encoder (conv3x3 + lrelu, fused stride-2 output subsample) ----
    run_conv(1, true, 1, x, IN(1),  IN(2),  A, 2,    3, 512, 512,   64, 256, 256);
    run_conv(1, true, 1, A, IN(3),  IN(4),  B, 2,   64, 256, 256,  128, 128, 128);
    run_conv(1, true, 2, B, IN(5),  IN(6),  A, 2,  128, 128, 128,  256,  64,  64);
    run_conv(1, true, 4, A, IN(7),  IN(8),  B, 2,  256,  64,  64,  512,  32,  32);
    run_conv(1, true, 4, B, IN(9),  IN(10), A, 2,  512,  32,  32, 1024,  16,  16);

    // ---- innermost: conv + BN(batch stats) + lrelu ----
    run_conv(0, false, 4, A, IN(11), IN(12), B, 2, 1024, 16, 16, 1024, 16, 16);
    bn_lrelu_kernel<<<1024, 256>>>(B, IN(13), IN(14), 2, 1024, 16 * 16);

    // ---- decoder (parity-decomposed transposed conv + lrelu) ----
    run_convT(8, B, IN(15), IN(16), A, 2, 1024, 16, 16,    512);
    run_convT(4, A, IN(17), IN(18), B, 2,  512, 32, 32,    256);
    run_convT(2, B, IN(19), IN(20), A, 2,  256, 64, 64,    128);
    run_convT(1, A, IN(21), IN(22), B, 2,  128, 128, 128,   64);
    run_convT(1, B, IN(23), IN(24), A, 2,   64, 256, 256,   64);

    // ---- 1x1 epilogue ----
    int HW = 512 * 512;
    int total4 = (2 * HW) >> 2;
    conv1x1_ep_kernel<<<(total4 + 255) / 256, 256>>>(A, IN(25), IN(26), O, 2, 64, HW);
#undef IN
}